// round 9
// baseline (speedup 1.0000x reference)
#include <cuda_runtime.h>

#define L  4096   // tokens (64x64)
#define CH 256    // channels
#define NH 16     // heads (head_dim = 4)
#define DEG 6
#define F  210    // monomials (a,b,c,d), a+b+c+d <= 6
#define NPAIR 28  // pairs (a,b), a+b <= 6
#define PPW 58    // PP row stride (28 + 28 + pad)

// Scratch (allocation-free rule: __device__ globals).
__device__ ulonglong2 g_q  [NH * L];        // normalized q
__device__ ulonglong2 g_k  [NH * L];        // normalized k
__device__ ulonglong2 g_v  [NH * L];        // raw V
__device__ float      g_attf[64 * L];       // att, o-major: [o = h*4+d][token]
__device__ float      g_Sp [NH * 16 * F];   // k-moment partials per block
__device__ float4     g_Mp [NH * 16 * F];   // q,vp-moment partials per block

// ---------- packed f32x2 helpers ----------
__device__ __forceinline__ unsigned long long ffma2(unsigned long long a,
                                                    unsigned long long b,
                                                    unsigned long long c) {
    unsigned long long d;
    asm("fma.rn.f32x2 %0, %1, %2, %3;" : "=l"(d) : "l"(a), "l"(b), "l"(c));
    return d;
}
__device__ __forceinline__ float2 unpk(unsigned long long v) {
    float2 f;
    asm("mov.b64 {%0, %1}, %2;" : "=f"(f.x), "=f"(f.y) : "l"(v));
    return f;
}
__device__ __forceinline__ unsigned long long pk(float x, float y) {
    unsigned long long v;
    asm("mov.b64 %0, {%1, %2};" : "=l"(v) : "f"(x), "f"(y));
    return v;
}

// ---------- monomial tables, computed inline ----------
// Chebyshev-truncated deg-6 coefficients of e^x on [-1,1] (max err ~3.4e-6)
__device__ __forceinline__ void alpha_decode(int t, int& A, int& B, int& C, int& D) {
    int idx = 0;
    for (int a = 0; a <= DEG; ++a)
        for (int b = 0; b <= DEG - a; ++b)
            for (int c = 0; c <= DEG - a - b; ++c) {
                const int dmax = DEG - a - b - c;
                if (t - idx <= dmax) { A = a; B = b; C = c; D = t - idx; return; }
                idx += dmax + 1;
            }
    A = B = C = D = 0;
}
__device__ __forceinline__ void monomial_info(int t, float& w, int& px, int& py) {
    const float cc[7] = {0.9999998013203132f, 1.0000222899985483f,
                         0.5000063476462252f, 0.1664888731563763f,
                         0.04163501123055814f, 0.0086868209906231f,
                         0.0014392748707944755f};
    const float fact[7] = {1.f, 1.f, 2.f, 6.f, 24.f, 120.f, 720.f};
    int a, b, c, d;
    alpha_decode(t, a, b, c, d);
    const int s = a + b + c + d;
    w  = cc[s] * fact[s] / (fact[a] * fact[b] * fact[c] * fact[d]);
    px = a * 7 - (a * (a - 1)) / 2 + b;
    py = NPAIR + c * 7 - (c * (c - 1)) / 2 + d;
}

// ---------- fill pairwise-product row for one token ----------
__device__ __forceinline__ void fill_pp_row(float* row, float x0, float x1,
                                            float x2, float x3) {
    float pw0[7], pw1[7], pw2[7], pw3[7];
    pw0[0] = pw1[0] = pw2[0] = pw3[0] = 1.0f;
#pragma unroll
    for (int p = 1; p <= DEG; ++p) {
        pw0[p] = pw0[p - 1] * x0; pw1[p] = pw1[p - 1] * x1;
        pw2[p] = pw2[p - 1] * x2; pw3[p] = pw3[p - 1] * x3;
    }
    int p = 0;
#pragma unroll
    for (int a = 0; a <= DEG; ++a)
#pragma unroll
        for (int b = 0; b <= DEG - a; ++b) row[p++] = pw0[a] * pw1[b];
    p = NPAIR;
#pragma unroll
    for (int c = 0; c <= DEG; ++c)
#pragma unroll
        for (int d = 0; d <= DEG - c; ++d) row[p++] = pw2[c] * pw3[d];
}

// ============ Kernel 1: QKV projection (packed FFMA2) + normalize + k-moment partials ============
// grid (16 l-tiles of 256, 16 heads), block 256.  (identical to the 66us R4 version)
__global__ void qkv_kmom_kernel(const float* __restrict__ X,
                                const float* __restrict__ Wq, const float* __restrict__ bq,
                                const float* __restrict__ Wk, const float* __restrict__ bk,
                                const float* __restrict__ Wv, const float* __restrict__ bv) {
    __shared__ __align__(16) float sbuf[128 * PPW];   // union: wsm[256][12] then PP[128][58]
    __shared__ ulonglong2 karr[256];
    const int tid = threadIdx.x;
    const int h   = blockIdx.y;
    const int l   = blockIdx.x * 256 + tid;

#pragma unroll
    for (int r = 0; r < 12; ++r) {
        const float* W = (r < 4) ? Wq : (r < 8) ? Wk : Wv;
        sbuf[tid * 12 + r] = W[(h * 4 + (r & 3)) * CH + tid];
    }
    __syncthreads();

    unsigned long long acc[6];
#pragma unroll
    for (int r = 0; r < 6; ++r) acc[r] = 0ULL;

#pragma unroll 4
    for (int c = 0; c < CH; ++c) {
        const float x = X[c * L + l];
        const unsigned long long xx = pk(x, x);
        const ulonglong2* w = (const ulonglong2*)&sbuf[c * 12];
        const ulonglong2 wA = w[0], wB = w[1], wC = w[2];
        acc[0] = ffma2(wA.x, xx, acc[0]); acc[1] = ffma2(wA.y, xx, acc[1]);
        acc[2] = ffma2(wB.x, xx, acc[2]); acc[3] = ffma2(wB.y, xx, acc[3]);
        acc[4] = ffma2(wC.x, xx, acc[4]); acc[5] = ffma2(wC.y, xx, acc[5]);
    }

    const int ob = h * 4;
    float2 f;
    f = unpk(acc[0]); float q0 = f.x + bq[ob],     q1 = f.y + bq[ob + 1];
    f = unpk(acc[1]); float q2 = f.x + bq[ob + 2], q3 = f.y + bq[ob + 3];
    f = unpk(acc[2]); float k0 = f.x + bk[ob],     k1 = f.y + bk[ob + 1];
    f = unpk(acc[3]); float k2 = f.x + bk[ob + 2], k3 = f.y + bk[ob + 3];
    f = unpk(acc[4]); float v0 = f.x + bv[ob],     v1 = f.y + bv[ob + 1];
    f = unpk(acc[5]); float v2 = f.x + bv[ob + 2], v3 = f.y + bv[ob + 3];

    const float nq = q0 * q0 + q1 * q1 + q2 * q2 + q3 * q3;
    const float iq = 1.0f / fmaxf(sqrtf(nq), 1e-12f);
    q0 *= iq; q1 *= iq; q2 *= iq; q3 *= iq;
    const float nk = k0 * k0 + k1 * k1 + k2 * k2 + k3 * k3;
    const float ik = 1.0f / fmaxf(sqrtf(nk), 1e-12f);
    k0 *= ik; k1 *= ik; k2 *= ik; k3 *= ik;

    const int idx = h * L + l;
    g_q[idx] = make_ulonglong2(pk(q0, q1), pk(q2, q3));
    const ulonglong2 kk = make_ulonglong2(pk(k0, k1), pk(k2, k3));
    g_k[idx] = kk;
    g_v[idx] = make_ulonglong2(pk(v0, v1), pk(v2, v3));
    karr[tid] = kk;

    int px = 0, py = 0; float wdummy;
    if (tid < F) monomial_info(tid, wdummy, px, py);

    float accS = 0.0f;
#pragma unroll
    for (int half = 0; half < 2; ++half) {
        __syncthreads();
        if (tid < 128) {
            const ulonglong2 kr = karr[half * 128 + tid];
            const float2 k01 = unpk(kr.x), k23 = unpk(kr.y);
            fill_pp_row(&sbuf[tid * PPW], k01.x, k01.y, k23.x, k23.y);
        }
        __syncthreads();
        if (tid < F) {
            float s0 = 0.f, s1 = 0.f;
#pragma unroll 4
            for (int i = 0; i < 128; i += 2) {
                s0 += sbuf[i * PPW + px] * sbuf[i * PPW + py];
                s1 += sbuf[(i + 1) * PPW + px] * sbuf[(i + 1) * PPW + py];
            }
            accS += s0 + s1;
        }
    }
    if (tid < F) g_Sp[(h * 16 + blockIdx.x) * F + tid] = accS;
}

// ============ Kernel 2: Z per j, vp = v/Z, q/vp-moment partials (fused) ============
// grid (16 j-tiles of 256, 16 heads), block 256.  (identical to R4)
__global__ void zvp_qmom_kernel() {
    __shared__ float Ssh[F];
    __shared__ ulonglong2 qarr[256];
    __shared__ ulonglong2 VPs[256];
    __shared__ __align__(16) float PPb[128 * PPW];
    const int tid = threadIdx.x;
    const int h   = blockIdx.y;
    const int j   = blockIdx.x * 256 + tid;

    int px = 0, py = 0;
    if (tid < F) {
        float w;
        monomial_info(tid, w, px, py);
        float s = 0.0f;
#pragma unroll
        for (int b = 0; b < 16; ++b) s += g_Sp[(h * 16 + b) * F + tid];
        Ssh[tid] = w * s;
    }
    const ulonglong2 qq = g_q[h * L + j];
    qarr[tid] = qq;
    __syncthreads();

    const float2 q01 = unpk(qq.x), q23 = unpk(qq.y);
    const float x0 = q01.x, x1 = q01.y, x2 = q23.x, x3 = q23.y;

    float accA = 0.f, accB = 0.f;
    {
        int idx = 0;
        float pa = 1.0f;
#pragma unroll
        for (int a = 0; a <= DEG; ++a) {
            float pab = pa;
#pragma unroll
            for (int b = 0; b <= DEG - a; ++b) {
                float pabc = pab;
#pragma unroll
                for (int c = 0; c <= DEG - a - b; ++c) {
                    float pabcd = pabc;
#pragma unroll
                    for (int d = 0; d <= DEG - a - b - c; ++d) {
                        if (idx & 1) accB = fmaf(pabcd, Ssh[idx], accB);
                        else         accA = fmaf(pabcd, Ssh[idx], accA);
                        idx++;
                        pabcd *= x3;
                    }
                    pabc *= x2;
                }
                pab *= x1;
            }
            pa *= x0;
        }
    }
    const float r = 1.0f / (accA + accB);
    const ulonglong2 vv = g_v[h * L + j];
    const float2 v01 = unpk(vv.x), v23 = unpk(vv.y);
    VPs[tid] = make_ulonglong2(pk(v01.x * r, v01.y * r), pk(v23.x * r, v23.y * r));

    unsigned long long a01 = 0ULL, a23 = 0ULL;
#pragma unroll
    for (int half = 0; half < 2; ++half) {
        __syncthreads();
        if (tid < 128) {
            const ulonglong2 qr = qarr[half * 128 + tid];
            const float2 a2 = unpk(qr.x), b2 = unpk(qr.y);
            fill_pp_row(&PPb[tid * PPW], a2.x, a2.y, b2.x, b2.y);
        }
        __syncthreads();
        if (tid < F) {
#pragma unroll 2
            for (int i = 0; i < 128; ++i) {
                const float m = PPb[i * PPW + px] * PPb[i * PPW + py];
                const unsigned long long mm = pk(m, m);
                const ulonglong2 vp = VPs[half * 128 + i];
                a01 = ffma2(vp.x, mm, a01);
                a23 = ffma2(vp.y, mm, a23);
            }
        }
    }
    if (tid < F) {
        const float2 r01 = unpk(a01), r23 = unpk(a23);
        g_Mp[(h * 16 + blockIdx.x) * F + tid] = make_float4(r01.x, r01.y, r23.x, r23.y);
    }
}

// ============ Kernel 3: out[d,i] = sum_alpha w_a M[d,alpha] k_i^alpha ============
// grid (32 i-tiles of 128, 16 heads), block 128.  (R4 compute; o-major stores)
__global__ void ceval_kernel() {
    __shared__ ulonglong2 Msh[F];
    const int t = threadIdx.x;
    const int h = blockIdx.y;
    const int i = blockIdx.x * 128 + t;

    for (int tt = t; tt < F; tt += 128) {
        float w; int px, py;
        monomial_info(tt, w, px, py);
        float4 s = make_float4(0.f, 0.f, 0.f, 0.f);
#pragma unroll
        for (int b = 0; b < 16; ++b) {
            const float4 p = g_Mp[(h * 16 + b) * F + tt];
            s.x += p.x; s.y += p.y; s.z += p.z; s.w += p.w;
        }
        Msh[tt] = make_ulonglong2(pk(w * s.x, w * s.y), pk(w * s.z, w * s.w));
    }
    __syncthreads();

    const ulonglong2 kk = g_k[h * L + i];
    const float2 k01 = unpk(kk.x), k23 = unpk(kk.y);
    const float x0 = k01.x, x1 = k01.y, x2 = k23.x, x3 = k23.y;

    unsigned long long a01A = 0ULL, a23A = 0ULL, a01B = 0ULL, a23B = 0ULL;
    int idx = 0;
    float pa = 1.0f;
#pragma unroll
    for (int a = 0; a <= DEG; ++a) {
        float pab = pa;
#pragma unroll
        for (int b = 0; b <= DEG - a; ++b) {
            float pabc = pab;
#pragma unroll
            for (int c = 0; c <= DEG - a - b; ++c) {
                float pabcd = pabc;
#pragma unroll
                for (int d = 0; d <= DEG - a - b - c; ++d) {
                    const unsigned long long mm = pk(pabcd, pabcd);
                    const ulonglong2 M = Msh[idx];
                    if (idx & 1) {
                        a01B = ffma2(mm, M.x, a01B);
                        a23B = ffma2(mm, M.y, a23B);
                    } else {
                        a01A = ffma2(mm, M.x, a01A);
                        a23A = ffma2(mm, M.y, a23A);
                    }
                    idx++;
                    pabcd *= x3;
                }
                pabc *= x2;
            }
            pab *= x1;
        }
        pa *= x0;
    }
    const float2 r01a = unpk(a01A), r01b = unpk(a01B);
    const float2 r23a = unpk(a23A), r23b = unpk(a23B);
    // o-major stores (coalesced across i within each o-row)
    g_attf[(h * 4 + 0) * L + i] = r01a.x + r01b.x;
    g_attf[(h * 4 + 1) * L + i] = r01a.y + r01b.y;
    g_attf[(h * 4 + 2) * L + i] = r23a.x + r23b.x;
    g_attf[(h * 4 + 3) * L + i] = r23a.y + r23b.y;
}

// ============ Kernel 4: output projection as register-tiled GEMM ============
// out(256 x 4096) = Wo(256 x 64) @ att(64 x 4096), + bias + residual.
// grid (64 token-tiles of 64, 4 channel-tiles of 64), block 256.
// thread (tx = tid&15 -> 4 tokens, ty = tid>>4 -> 4 channels); 16 packed accumulators.
__global__ void __launch_bounds__(256) oproj_kernel(
        const float* __restrict__ X,
        const float* __restrict__ Wo,
        const float* __restrict__ bo,
        float* __restrict__ out) {
    __shared__ __align__(16) float attsm[64 * 64];                 // [o][t]  16 KB
    __shared__ __align__(16) unsigned long long WoP[64 * 64];      // [cc][o] pairs, 32 KB
    const int tid   = threadIdx.x;
    const int tx    = tid & 15;
    const int ty    = tid >> 4;
    const int lbase = blockIdx.x * 64;
    const int cbase = blockIdx.y * 64;

    // stage att tile: 64 o-rows x 64 tokens (coalesced float4)
    for (int e4 = tid; e4 < 64 * 16; e4 += 256) {
        const int o = e4 >> 4, t4 = (e4 & 15) * 4;
        *(float4*)&attsm[o * 64 + t4] = *(const float4*)&g_attf[o * L + lbase + t4];
    }
    // stage Wo tile as (w,w) pairs, [cc][o] (coalesced gmem, conflict-free smem)
    for (int e = tid; e < 64 * 64; e += 256) {
        const int cc = e >> 6, o = e & 63;
        const float w = Wo[(cbase + cc) * 64 + o];
        WoP[cc * 64 + o] = pk(w, w);
    }
    __syncthreads();

    unsigned long long acc[4][2];
#pragma unroll
    for (int cc = 0; cc < 4; ++cc) { acc[cc][0] = 0ULL; acc[cc][1] = 0ULL; }

    const unsigned long long* w0 = &WoP[(ty * 4 + 0) * 64];
    const unsigned long long* w1 = &WoP[(ty * 4 + 1) * 64];
    const unsigned long long* w2 = &WoP[(ty * 4 + 2) * 64];
    const unsigned long long* w3 = &WoP[(ty * 4 + 3) * 64];

#pragma unroll 4
    for (int o = 0; o < 64; ++o) {
        const ulonglong2 av = *(const ulonglong2*)&attsm[o * 64 + tx * 4];
        const unsigned long long wv0 = w0[o], wv1 = w1[o], wv2 = w2[o], wv3 = w3[o];
        acc[0][0] = ffma2(wv0, av.x, acc[0][0]); acc[0][1] = ffma2(wv0, av.y, acc[0][1]);
        acc[1][0] = ffma2(wv1, av.x, acc[1][0]); acc[1][1] = ffma2(wv1, av.y, acc[1][1]);
        acc[2][0] = ffma2(wv2, av.x, acc[2][0]); acc[2][1] = ffma2(wv2, av.y, acc[2][1]);
        acc[3][0] = ffma2(wv3, av.x, acc[3][0]); acc[3][1] = ffma2(wv3, av.y, acc[3][1]);
    }

    const int l0 = lbase + tx * 4;
#pragma unroll
    for (int cc = 0; cc < 4; ++cc) {
        const int c = cbase + ty * 4 + cc;
        const float bc = bo[c];
        const float2 p0 = unpk(acc[cc][0]), p1 = unpk(acc[cc][1]);
        const float4 xr = *(const float4*)&X[c * L + l0];
        float4 o4;
        o4.x = xr.x + bc + p0.x;
        o4.y = xr.y + bc + p0.y;
        o4.z = xr.z + bc + p1.x;
        o4.w = xr.w + bc + p1.y;
        *(float4*)&out[c * L + l0] = o4;
    }
}

extern "C" void kernel_launch(void* const* d_in, const int* in_sizes, int n_in,
                              void* d_out, int out_size) {
    (void)in_sizes; (void)n_in; (void)out_size;
    const float* X  = (const float*)d_in[0];
    const float* Wq = (const float*)d_in[1];
    const float* bq = (const float*)d_in[2];
    const float* Wk = (const float*)d_in[3];
    const float* bk = (const float*)d_in[4];
    const float* Wv = (const float*)d_in[5];
    const float* bv = (const float*)d_in[6];
    const float* Wo = (const float*)d_in[7];
    const float* bo = (const float*)d_in[8];
    float* out = (float*)d_out;

    qkv_kmom_kernel<<<dim3(16, 16), 256>>>(X, Wq, bq, Wk, bk, Wv, bv);
    zvp_qmom_kernel<<<dim3(16, 16), 256>>>();
    ceval_kernel   <<<dim3(32, 16), 128>>>();
    oproj_kernel   <<<dim3(64, 4),  256>>>(X, Wo, bo, out);
}

// round 13
// speedup vs baseline: 1.6084x; 1.6084x over previous
#include <cuda_runtime.h>

#define L  4096   // tokens (64x64)
#define CH 256    // channels
#define NH 16     // heads (head_dim = 4)
#define DEG 6
#define F  210    // monomials (a,b,c,d), a+b+c+d <= 6
#define NPAIR 28  // pairs (a,b), a+b <= 6
#define PPW 58    // PP row stride (28 + 28 + pad)

// Scratch (allocation-free rule: __device__ globals).
__device__ ulonglong2 g_q  [NH * L];        // normalized q
__device__ ulonglong2 g_k  [NH * L];        // normalized k
__device__ ulonglong2 g_v  [NH * L];        // raw V
__device__ ulonglong2 g_att[NH * L];        // out[d, i] per head
__device__ float      g_Sp [NH * 16 * F];   // k-moment partials per block
__device__ float4     g_Mp [NH * 16 * F];   // q,vp-moment partials per block

// ---------- packed f32x2 helpers ----------
__device__ __forceinline__ unsigned long long ffma2(unsigned long long a,
                                                    unsigned long long b,
                                                    unsigned long long c) {
    unsigned long long d;
    asm("fma.rn.f32x2 %0, %1, %2, %3;" : "=l"(d) : "l"(a), "l"(b), "l"(c));
    return d;
}
__device__ __forceinline__ float2 unpk(unsigned long long v) {
    float2 f;
    asm("mov.b64 {%0, %1}, %2;" : "=f"(f.x), "=f"(f.y) : "l"(v));
    return f;
}
__device__ __forceinline__ unsigned long long pk(float x, float y) {
    unsigned long long v;
    asm("mov.b64 %0, {%1, %2};" : "=l"(v) : "f"(x), "f"(y));
    return v;
}

// ---------- monomial tables, computed inline ----------
// Chebyshev-truncated deg-6 coefficients of e^x on [-1,1] (max err ~3.4e-6)
__device__ __forceinline__ void alpha_decode(int t, int& A, int& B, int& C, int& D) {
    int idx = 0;
    for (int a = 0; a <= DEG; ++a)
        for (int b = 0; b <= DEG - a; ++b)
            for (int c = 0; c <= DEG - a - b; ++c) {
                const int dmax = DEG - a - b - c;
                if (t - idx <= dmax) { A = a; B = b; C = c; D = t - idx; return; }
                idx += dmax + 1;
            }
    A = B = C = D = 0;
}
__device__ __forceinline__ void monomial_info(int t, float& w, int& px, int& py) {
    const float cc[7] = {0.9999998013203132f, 1.0000222899985483f,
                         0.5000063476462252f, 0.1664888731563763f,
                         0.04163501123055814f, 0.0086868209906231f,
                         0.0014392748707944755f};
    const float fact[7] = {1.f, 1.f, 2.f, 6.f, 24.f, 120.f, 720.f};
    int a, b, c, d;
    alpha_decode(t, a, b, c, d);
    const int s = a + b + c + d;
    w  = cc[s] * fact[s] / (fact[a] * fact[b] * fact[c] * fact[d]);
    px = a * 7 - (a * (a - 1)) / 2 + b;
    py = NPAIR + c * 7 - (c * (c - 1)) / 2 + d;
}

// ---------- fill pairwise-product row for one token ----------
__device__ __forceinline__ void fill_pp_row(float* row, float x0, float x1,
                                            float x2, float x3) {
    float pw0[7], pw1[7], pw2[7], pw3[7];
    pw0[0] = pw1[0] = pw2[0] = pw3[0] = 1.0f;
#pragma unroll
    for (int p = 1; p <= DEG; ++p) {
        pw0[p] = pw0[p - 1] * x0; pw1[p] = pw1[p - 1] * x1;
        pw2[p] = pw2[p - 1] * x2; pw3[p] = pw3[p - 1] * x3;
    }
    int p = 0;
#pragma unroll
    for (int a = 0; a <= DEG; ++a)
#pragma unroll
        for (int b = 0; b <= DEG - a; ++b) row[p++] = pw0[a] * pw1[b];
    p = NPAIR;
#pragma unroll
    for (int c = 0; c <= DEG; ++c)
#pragma unroll
        for (int d = 0; d <= DEG - c; ++d) row[p++] = pw2[c] * pw3[d];
}

// ============ Kernel 1: QKV projection (packed FFMA2) + normalize + k-moment partials ============
// grid (16 l-tiles of 256, 16 heads), block 256.  (identical to the 66us R4 version)
__global__ void qkv_kmom_kernel(const float* __restrict__ X,
                                const float* __restrict__ Wq, const float* __restrict__ bq,
                                const float* __restrict__ Wk, const float* __restrict__ bk,
                                const float* __restrict__ Wv, const float* __restrict__ bv) {
    __shared__ __align__(16) float sbuf[128 * PPW];   // union: wsm[256][12] then PP[128][58]
    __shared__ ulonglong2 karr[256];
    const int tid = threadIdx.x;
    const int h   = blockIdx.y;
    const int l   = blockIdx.x * 256 + tid;

#pragma unroll
    for (int r = 0; r < 12; ++r) {
        const float* W = (r < 4) ? Wq : (r < 8) ? Wk : Wv;
        sbuf[tid * 12 + r] = W[(h * 4 + (r & 3)) * CH + tid];
    }
    __syncthreads();

    unsigned long long acc[6];
#pragma unroll
    for (int r = 0; r < 6; ++r) acc[r] = 0ULL;

#pragma unroll 4
    for (int c = 0; c < CH; ++c) {
        const float x = X[c * L + l];
        const unsigned long long xx = pk(x, x);
        const ulonglong2* w = (const ulonglong2*)&sbuf[c * 12];
        const ulonglong2 wA = w[0], wB = w[1], wC = w[2];
        acc[0] = ffma2(wA.x, xx, acc[0]); acc[1] = ffma2(wA.y, xx, acc[1]);
        acc[2] = ffma2(wB.x, xx, acc[2]); acc[3] = ffma2(wB.y, xx, acc[3]);
        acc[4] = ffma2(wC.x, xx, acc[4]); acc[5] = ffma2(wC.y, xx, acc[5]);
    }

    const int ob = h * 4;
    float2 f;
    f = unpk(acc[0]); float q0 = f.x + bq[ob],     q1 = f.y + bq[ob + 1];
    f = unpk(acc[1]); float q2 = f.x + bq[ob + 2], q3 = f.y + bq[ob + 3];
    f = unpk(acc[2]); float k0 = f.x + bk[ob],     k1 = f.y + bk[ob + 1];
    f = unpk(acc[3]); float k2 = f.x + bk[ob + 2], k3 = f.y + bk[ob + 3];
    f = unpk(acc[4]); float v0 = f.x + bv[ob],     v1 = f.y + bv[ob + 1];
    f = unpk(acc[5]); float v2 = f.x + bv[ob + 2], v3 = f.y + bv[ob + 3];

    const float nq = q0 * q0 + q1 * q1 + q2 * q2 + q3 * q3;
    const float iq = 1.0f / fmaxf(sqrtf(nq), 1e-12f);
    q0 *= iq; q1 *= iq; q2 *= iq; q3 *= iq;
    const float nk = k0 * k0 + k1 * k1 + k2 * k2 + k3 * k3;
    const float ik = 1.0f / fmaxf(sqrtf(nk), 1e-12f);
    k0 *= ik; k1 *= ik; k2 *= ik; k3 *= ik;

    const int idx = h * L + l;
    g_q[idx] = make_ulonglong2(pk(q0, q1), pk(q2, q3));
    const ulonglong2 kk = make_ulonglong2(pk(k0, k1), pk(k2, k3));
    g_k[idx] = kk;
    g_v[idx] = make_ulonglong2(pk(v0, v1), pk(v2, v3));
    karr[tid] = kk;

    int px = 0, py = 0; float wdummy;
    if (tid < F) monomial_info(tid, wdummy, px, py);

    float accS = 0.0f;
#pragma unroll
    for (int half = 0; half < 2; ++half) {
        __syncthreads();
        if (tid < 128) {
            const ulonglong2 kr = karr[half * 128 + tid];
            const float2 k01 = unpk(kr.x), k23 = unpk(kr.y);
            fill_pp_row(&sbuf[tid * PPW], k01.x, k01.y, k23.x, k23.y);
        }
        __syncthreads();
        if (tid < F) {
            float s0 = 0.f, s1 = 0.f;
#pragma unroll 4
            for (int i = 0; i < 128; i += 2) {
                s0 += sbuf[i * PPW + px] * sbuf[i * PPW + py];
                s1 += sbuf[(i + 1) * PPW + px] * sbuf[(i + 1) * PPW + py];
            }
            accS += s0 + s1;
        }
    }
    if (tid < F) g_Sp[(h * 16 + blockIdx.x) * F + tid] = accS;
}

// ============ Kernel 2: Z per j, vp = v/Z, q/vp-moment partials (fused) ============
// grid (16 j-tiles of 256, 16 heads), block 256.  (identical to R4)
__global__ void zvp_qmom_kernel() {
    __shared__ float Ssh[F];
    __shared__ ulonglong2 qarr[256];
    __shared__ ulonglong2 VPs[256];
    __shared__ __align__(16) float PPb[128 * PPW];
    const int tid = threadIdx.x;
    const int h   = blockIdx.y;
    const int j   = blockIdx.x * 256 + tid;

    int px = 0, py = 0;
    if (tid < F) {
        float w;
        monomial_info(tid, w, px, py);
        float s = 0.0f;
#pragma unroll
        for (int b = 0; b < 16; ++b) s += g_Sp[(h * 16 + b) * F + tid];
        Ssh[tid] = w * s;
    }
    const ulonglong2 qq = g_q[h * L + j];
    qarr[tid] = qq;
    __syncthreads();

    const float2 q01 = unpk(qq.x), q23 = unpk(qq.y);
    const float x0 = q01.x, x1 = q01.y, x2 = q23.x, x3 = q23.y;

    float accA = 0.f, accB = 0.f;
    {
        int idx = 0;
        float pa = 1.0f;
#pragma unroll
        for (int a = 0; a <= DEG; ++a) {
            float pab = pa;
#pragma unroll
            for (int b = 0; b <= DEG - a; ++b) {
                float pabc = pab;
#pragma unroll
                for (int c = 0; c <= DEG - a - b; ++c) {
                    float pabcd = pabc;
#pragma unroll
                    for (int d = 0; d <= DEG - a - b - c; ++d) {
                        if (idx & 1) accB = fmaf(pabcd, Ssh[idx], accB);
                        else         accA = fmaf(pabcd, Ssh[idx], accA);
                        idx++;
                        pabcd *= x3;
                    }
                    pabc *= x2;
                }
                pab *= x1;
            }
            pa *= x0;
        }
    }
    const float r = 1.0f / (accA + accB);
    const ulonglong2 vv = g_v[h * L + j];
    const float2 v01 = unpk(vv.x), v23 = unpk(vv.y);
    VPs[tid] = make_ulonglong2(pk(v01.x * r, v01.y * r), pk(v23.x * r, v23.y * r));

    unsigned long long a01 = 0ULL, a23 = 0ULL;
#pragma unroll
    for (int half = 0; half < 2; ++half) {
        __syncthreads();
        if (tid < 128) {
            const ulonglong2 qr = qarr[half * 128 + tid];
            const float2 a2 = unpk(qr.x), b2 = unpk(qr.y);
            fill_pp_row(&PPb[tid * PPW], a2.x, a2.y, b2.x, b2.y);
        }
        __syncthreads();
        if (tid < F) {
#pragma unroll 2
            for (int i = 0; i < 128; ++i) {
                const float m = PPb[i * PPW + px] * PPb[i * PPW + py];
                const unsigned long long mm = pk(m, m);
                const ulonglong2 vp = VPs[half * 128 + i];
                a01 = ffma2(vp.x, mm, a01);
                a23 = ffma2(vp.y, mm, a23);
            }
        }
    }
    if (tid < F) {
        const float2 r01 = unpk(a01), r23 = unpk(a23);
        g_Mp[(h * 16 + blockIdx.x) * F + tid] = make_float4(r01.x, r01.y, r23.x, r23.y);
    }
}

// ============ Kernel 3: out[d,i] = sum_alpha w_a M[d,alpha] k_i^alpha ============
// grid (32 i-tiles of 128, 16 heads), block 128.  (identical to R4)
__global__ void ceval_kernel() {
    __shared__ ulonglong2 Msh[F];
    const int t = threadIdx.x;
    const int h = blockIdx.y;
    const int i = blockIdx.x * 128 + t;

    for (int tt = t; tt < F; tt += 128) {
        float w; int px, py;
        monomial_info(tt, w, px, py);
        float4 s = make_float4(0.f, 0.f, 0.f, 0.f);
#pragma unroll
        for (int b = 0; b < 16; ++b) {
            const float4 p = g_Mp[(h * 16 + b) * F + tt];
            s.x += p.x; s.y += p.y; s.z += p.z; s.w += p.w;
        }
        Msh[tt] = make_ulonglong2(pk(w * s.x, w * s.y), pk(w * s.z, w * s.w));
    }
    __syncthreads();

    const ulonglong2 kk = g_k[h * L + i];
    const float2 k01 = unpk(kk.x), k23 = unpk(kk.y);
    const float x0 = k01.x, x1 = k01.y, x2 = k23.x, x3 = k23.y;

    unsigned long long a01A = 0ULL, a23A = 0ULL, a01B = 0ULL, a23B = 0ULL;
    int idx = 0;
    float pa = 1.0f;
#pragma unroll
    for (int a = 0; a <= DEG; ++a) {
        float pab = pa;
#pragma unroll
        for (int b = 0; b <= DEG - a; ++b) {
            float pabc = pab;
#pragma unroll
            for (int c = 0; c <= DEG - a - b; ++c) {
                float pabcd = pabc;
#pragma unroll
                for (int d = 0; d <= DEG - a - b - c; ++d) {
                    const unsigned long long mm = pk(pabcd, pabcd);
                    const ulonglong2 M = Msh[idx];
                    if (idx & 1) {
                        a01B = ffma2(mm, M.x, a01B);
                        a23B = ffma2(mm, M.y, a23B);
                    } else {
                        a01A = ffma2(mm, M.x, a01A);
                        a23A = ffma2(mm, M.y, a23A);
                    }
                    idx++;
                    pabcd *= x3;
                }
                pabc *= x2;
            }
            pab *= x1;
        }
        pa *= x0;
    }
    const float2 r01a = unpk(a01A), r01b = unpk(a01B);
    const float2 r23a = unpk(a23A), r23b = unpk(a23B);
    g_att[h * L + i] = make_ulonglong2(pk(r01a.x + r01b.x, r01a.y + r01b.y),
                                       pk(r23a.x + r23b.x, r23a.y + r23b.y));
}

// ============ Kernel 4: output projection + bias + residual ============
// grid (32 l-tiles of 128, 32 c-groups of 8), block 128.  (identical to the R2
// version measured at 11.5us — the fastest oproj of the session)
__global__ void oproj_kernel(const float* __restrict__ X,
                             const float* __restrict__ Wo,
                             const float* __restrict__ bo,
                             float* __restrict__ out) {
    __shared__ __align__(16) float wsm[8][64];
    const int tid = threadIdx.x;
    const int cg  = blockIdx.y;
    const int l   = blockIdx.x * 128 + tid;

    for (int idx = tid; idx < 512; idx += 128) {
        const int cc = idx >> 6, o = idx & 63;
        wsm[cc][o] = Wo[(cg * 8 + cc) * 64 + o];
    }
    __syncthreads();

    unsigned long long acc[8];
#pragma unroll
    for (int cc = 0; cc < 8; ++cc) acc[cc] = 0ULL;

#pragma unroll
    for (int hh = 0; hh < NH; ++hh) {
        const ulonglong2 a = g_att[hh * L + l];
#pragma unroll
        for (int cc = 0; cc < 8; ++cc) {
            const ulonglong2 w = *(const ulonglong2*)&wsm[cc][hh * 4];
            acc[cc] = ffma2(a.x, w.x, acc[cc]);
            acc[cc] = ffma2(a.y, w.y, acc[cc]);
        }
    }
#pragma unroll
    for (int cc = 0; cc < 8; ++cc) {
        const int c = cg * 8 + cc;
        const float2 f = unpk(acc[cc]);
        out[c * L + l] = X[c * L + l] + bo[c] + f.x + f.y;
    }
}

extern "C" void kernel_launch(void* const* d_in, const int* in_sizes, int n_in,
                              void* d_out, int out_size) {
    (void)in_sizes; (void)n_in; (void)out_size;
    const float* X  = (const float*)d_in[0];
    const float* Wq = (const float*)d_in[1];
    const float* bq = (const float*)d_in[2];
    const float* Wk = (const float*)d_in[3];
    const float* bk = (const float*)d_in[4];
    const float* Wv = (const float*)d_in[5];
    const float* bv = (const float*)d_in[6];
    const float* Wo = (const float*)d_in[7];
    const float* bo = (const float*)d_in[8];
    float* out = (float*)d_out;

    qkv_kmom_kernel<<<dim3(16, 16), 256>>>(X, Wq, bq, Wk, bk, Wv, bv);
    zvp_qmom_kernel<<<dim3(16, 16), 256>>>();
    ceval_kernel   <<<dim3(32, 16), 128>>>();
    oproj_kernel   <<<dim3(32, 32), 128>>>(X, Wo, bo, out);
}